// round 1
// baseline (speedup 1.0000x reference)
#include <cuda_runtime.h>
#include <cuda_fp16.h>
#include <cstdint>
#include <cstddef>

#define B_ 2048
#define T_ 200
#define D_ 4
#define H_ 256
#define G_ 1024   // 4*H

#define BM 128
#define BN 128
#define BK 64
#define SGP 132   // gate smem pitch (floats)

// ------------------------- device scratch (no allocs allowed) -------------------------
__device__ __align__(128) __half g_Wh0[G_ * H_];          // [1024][256] packed, gate-interleaved rows
__device__ __align__(128) float  g_Wx0[G_ * D_];          // [1024][4]
__device__ __align__(128) float  g_bias0[G_];
__device__ __align__(128) __half g_W1[G_ * 2 * H_];       // [1024][512]: cols 0..255 = W_ih1, 256..511 = W_hh1
__device__ __align__(128) float  g_bias1[G_];
__device__ __align__(128) __half g_zero16[B_ * H_];       // zero h for t=0 (never written after init)
__device__ __align__(128) float  g_c0[B_ * H_];
__device__ __align__(128) float  g_c1[B_ * H_];
__device__ __align__(128) __half g_h1seq[(size_t)T_ * B_ * H_];  // layer0 output sequence (and its own state chain)
__device__ __align__(128) __half g_h2a[B_ * H_];
__device__ __align__(128) __half g_h2b[B_ * H_];
__device__ __align__(128) float  g_h2f[B_ * H_];          // fp32 h2 at t = T-1 (FC input)

// ------------------------- init / pack -------------------------
__global__ void k_init() {
    int stride = gridDim.x * blockDim.x;
    for (int i = blockIdx.x * blockDim.x + threadIdx.x; i < B_ * H_; i += stride) {
        g_zero16[i] = __float2half(0.f);
        g_c0[i] = 0.f;
        g_c1[i] = 0.f;
    }
}

__global__ void k_pack0(const float* __restrict__ W_ih0, const float* __restrict__ W_hh0,
                        const float* __restrict__ b_ih0, const float* __restrict__ b_hh0) {
    int stride = gridDim.x * blockDim.x;
    for (int i = blockIdx.x * blockDim.x + threadIdx.x; i < G_ * H_; i += stride) {
        int n = i >> 8;          // packed gate-col 0..1023
        int k = i & 255;
        int j = n >> 2, g = n & 3;
        int orow = g * H_ + j;   // original row in [4H, *] layout
        g_Wh0[i] = __float2half(W_hh0[orow * H_ + k]);
        if (k < D_) g_Wx0[n * D_ + k] = W_ih0[orow * D_ + k];
        if (k == 0) g_bias0[n] = b_ih0[orow] + b_hh0[orow];
    }
}

__global__ void k_pack1(const float* __restrict__ W_ih1, const float* __restrict__ W_hh1,
                        const float* __restrict__ b_ih1, const float* __restrict__ b_hh1) {
    int stride = gridDim.x * blockDim.x;
    for (int i = blockIdx.x * blockDim.x + threadIdx.x; i < G_ * 2 * H_; i += stride) {
        int n = i >> 9;
        int k = i & 511;
        int j = n >> 2, g = n & 3;
        int orow = g * H_ + j;
        float v = (k < H_) ? W_ih1[orow * H_ + k] : W_hh1[orow * H_ + (k - H_)];
        g_W1[i] = __float2half(v);
        if (k == 0) g_bias1[n] = b_ih1[orow] + b_hh1[orow];
    }
}

// ------------------------- fused LSTM step (GEMM + pointwise) -------------------------
// gates[b, n] = sum_k A[b,k] * W[n,k]  (+ bias + optional x@Wx), n gate-interleaved.
// A = concat(a0[256], a1[256]) for KTOT=512; a0 only for KTOT=256.
__global__ __launch_bounds__(256, 1)
void k_step(const __half* __restrict__ a0, const __half* __restrict__ a1,
            const __half* __restrict__ W, int KTOT,
            const float* __restrict__ bias,
            const float* __restrict__ x, int t,               // x: [B,T,4] (layer0) or null
            const float* __restrict__ Wx,                     // [1024][4] or null
            float* __restrict__ c,
            __half* __restrict__ hout,
            float* __restrict__ houtf)
{
    extern __shared__ char smem[];
    __half* sAbase = (__half*)smem;                 // 2 stages x 16KB
    __half* sBbase = (__half*)(smem + 32768);       // 2 stages x 16KB
    float*  sg     = (float*)smem;                  // reused after GEMM: 128 x 132 fp32 (67.5KB)

    const int tid  = threadIdx.x;
    const int lane = tid & 31;
    const int warp = tid >> 5;
    const int wm = warp & 3;    // 4 M-warps (32 rows each)
    const int wn = warp >> 2;   // 2 N-warps (64 cols each)
    const int mbase = blockIdx.y * BM;
    const int nbase = blockIdx.x * BN;

    // ldmatrix per-thread decode
    const int lg = lane >> 3;
    const int lr = lane & 7;
    const int a_rowoff = lr + ((lg & 1) << 3);   // within m16 tile
    const int a_half   = lg >> 1;                // 0: k 0..7, 1: k 8..15
    const int b_rowoff = lr + ((lg >> 1) << 3);  // within 16 n-rows
    const int b_half   = lg & 1;

    float acc[2][8][4];
#pragma unroll
    for (int mi = 0; mi < 2; mi++)
#pragma unroll
        for (int nj = 0; nj < 8; nj++)
#pragma unroll
            for (int e = 0; e < 4; e++) acc[mi][nj][e] = 0.f;

    const int NKC = KTOT / BK;

    auto load_tiles = [&](int kc, int buf) {
        const int k0 = kc * BK;
        const __half* asrc = (k0 < H_) ? (a0 + k0) : (a1 + (k0 - H_));
        __half* sA = sAbase + buf * (BM * BK);
        __half* sB = sBbase + buf * (BN * BK);
#pragma unroll
        for (int i = 0; i < 4; i++) {
            int lin = tid + i * 256;          // 0..1023: 128 rows x 8 chunks of 16B
            int r = lin >> 3;
            int cch = lin & 7;
            int sc = cch ^ (r & 7);
            {   // A tile: rows = batch, stride H_ halves
                const __half* gp = asrc + (size_t)(mbase + r) * H_ + cch * 8;
                uint32_t sa = (uint32_t)__cvta_generic_to_shared(sA + r * BK + sc * 8);
                asm volatile("cp.async.cg.shared.global [%0], [%1], 16;\n" :: "r"(sa), "l"(gp));
            }
            {   // B tile: rows = gate col, stride KTOT halves
                const __half* gp = W + (size_t)(nbase + r) * KTOT + k0 + cch * 8;
                uint32_t sa = (uint32_t)__cvta_generic_to_shared(sB + r * BK + sc * 8);
                asm volatile("cp.async.cg.shared.global [%0], [%1], 16;\n" :: "r"(sa), "l"(gp));
            }
        }
        asm volatile("cp.async.commit_group;\n");
    };

    load_tiles(0, 0);

#pragma unroll 1
    for (int kc = 0; kc < NKC; kc++) {
        asm volatile("cp.async.wait_group 0;\n");
        __syncthreads();
        const int cur = kc & 1;
        if (kc + 1 < NKC) load_tiles(kc + 1, cur ^ 1);

        __half* sA = sAbase + cur * (BM * BK);
        __half* sB = sBbase + cur * (BN * BK);

#pragma unroll
        for (int k16 = 0; k16 < BK / 16; k16++) {
            uint32_t afr[2][4];
#pragma unroll
            for (int mi = 0; mi < 2; mi++) {
                int r = wm * 32 + mi * 16 + a_rowoff;
                int cch = (k16 * 2 + a_half) ^ (r & 7);
                uint32_t ad = (uint32_t)__cvta_generic_to_shared(sA + r * BK + cch * 8);
                asm volatile("ldmatrix.sync.aligned.m8n8.x4.shared.b16 {%0,%1,%2,%3}, [%4];\n"
                             : "=r"(afr[mi][0]), "=r"(afr[mi][1]), "=r"(afr[mi][2]), "=r"(afr[mi][3])
                             : "r"(ad));
            }
            uint32_t bfr[4][4];
#pragma unroll
            for (int np = 0; np < 4; np++) {
                int r = wn * 64 + np * 16 + b_rowoff;
                int cch = (k16 * 2 + b_half) ^ (r & 7);
                uint32_t ad = (uint32_t)__cvta_generic_to_shared(sB + r * BK + cch * 8);
                asm volatile("ldmatrix.sync.aligned.m8n8.x4.shared.b16 {%0,%1,%2,%3}, [%4];\n"
                             : "=r"(bfr[np][0]), "=r"(bfr[np][1]), "=r"(bfr[np][2]), "=r"(bfr[np][3])
                             : "r"(ad));
            }
#pragma unroll
            for (int mi = 0; mi < 2; mi++)
#pragma unroll
                for (int nj = 0; nj < 8; nj++) {
                    uint32_t b0 = bfr[nj >> 1][(nj & 1) * 2 + 0];
                    uint32_t b1 = bfr[nj >> 1][(nj & 1) * 2 + 1];
                    asm volatile(
                        "mma.sync.aligned.m16n8k16.row.col.f32.f16.f16.f32 "
                        "{%0,%1,%2,%3}, {%4,%5,%6,%7}, {%8,%9}, {%0,%1,%2,%3};\n"
                        : "+f"(acc[mi][nj][0]), "+f"(acc[mi][nj][1]),
                          "+f"(acc[mi][nj][2]), "+f"(acc[mi][nj][3])
                        : "r"(afr[mi][0]), "r"(afr[mi][1]), "r"(afr[mi][2]), "r"(afr[mi][3]),
                          "r"(b0), "r"(b1));
                }
        }
    }
    __syncthreads();   // all smem reads done; safe to overwrite with gates

    // scatter accumulators to gate smem
#pragma unroll
    for (int mi = 0; mi < 2; mi++)
#pragma unroll
        for (int nj = 0; nj < 8; nj++) {
            int r0 = wm * 32 + mi * 16 + (lane >> 2);
            int c0 = wn * 64 + nj * 8 + (lane & 3) * 2;
            sg[r0 * SGP + c0]           = acc[mi][nj][0];
            sg[r0 * SGP + c0 + 1]       = acc[mi][nj][1];
            sg[(r0 + 8) * SGP + c0]     = acc[mi][nj][2];
            sg[(r0 + 8) * SGP + c0 + 1] = acc[mi][nj][3];
        }
    __syncthreads();

    // pointwise LSTM cell update: each thread handles (row, hidden) pairs
    for (int idx = tid; idx < BM * 32; idx += 256) {
        int r  = idx >> 5;
        int jh = idx & 31;
        int b  = mbase + r;
        int nloc = jh * 4;
        int ng = nbase + nloc;           // global packed gate col of gate i

        float gi = sg[r * SGP + nloc + 0] + bias[ng + 0];
        float gf = sg[r * SGP + nloc + 1] + bias[ng + 1];
        float gg = sg[r * SGP + nloc + 2] + bias[ng + 2];
        float go = sg[r * SGP + nloc + 3] + bias[ng + 3];

        if (x) {  // layer0: tiny D=4 input projection, exact fp32
            const float* xr = x + ((size_t)b * T_ + t) * D_;
            float x0 = xr[0], x1 = xr[1], x2 = xr[2], x3 = xr[3];
            const float* w = Wx + (size_t)ng * D_;
            gi += x0 * w[0]  + x1 * w[1]  + x2 * w[2]  + x3 * w[3];
            gf += x0 * w[4]  + x1 * w[5]  + x2 * w[6]  + x3 * w[7];
            gg += x0 * w[8]  + x1 * w[9]  + x2 * w[10] + x3 * w[11];
            go += x0 * w[12] + x1 * w[13] + x2 * w[14] + x3 * w[15];
        }

        float i_ = 1.f / (1.f + expf(-gi));
        float f_ = 1.f / (1.f + expf(-gf));
        float g_ = tanhf(gg);
        float o_ = 1.f / (1.f + expf(-go));

        int jglob = (nbase >> 2) + jh;
        size_t ci = (size_t)b * H_ + jglob;
        float cn = f_ * c[ci] + i_ * g_;
        c[ci] = cn;
        float h = o_ * tanhf(cn);
        hout[ci] = __float2half(h);
        if (houtf) houtf[ci] = h;
    }
}

// ------------------------- final FC: out = h2_last @ W_fc.T + b_fc -------------------------
__global__ void k_fc(const float* __restrict__ h, const float* __restrict__ Wfc,
                     const float* __restrict__ bfc, float* __restrict__ out) {
    int b = blockIdx.x;
    int o = threadIdx.y;   // 0..5
    int lane = threadIdx.x;
    const float* hr = h + (size_t)b * H_;
    const float* wr = Wfc + (size_t)o * H_;
    float s = 0.f;
    for (int j = lane; j < H_; j += 32) s += hr[j] * wr[j];
#pragma unroll
    for (int off = 16; off; off >>= 1) s += __shfl_xor_sync(0xffffffffu, s, off);
    if (lane == 0) out[b * 6 + o] = s + bfc[o];
}

// ------------------------- host -------------------------
extern "C" void kernel_launch(void* const* d_in, const int* in_sizes, int n_in,
                              void* d_out, int out_size) {
    const float* x     = (const float*)d_in[0];
    const float* W_ih0 = (const float*)d_in[1];
    const float* W_hh0 = (const float*)d_in[2];
    const float* b_ih0 = (const float*)d_in[3];
    const float* b_hh0 = (const float*)d_in[4];
    const float* W_ih1 = (const float*)d_in[5];
    const float* W_hh1 = (const float*)d_in[6];
    const float* b_ih1 = (const float*)d_in[7];
    const float* b_hh1 = (const float*)d_in[8];
    const float* W_fc  = (const float*)d_in[9];
    const float* b_fc  = (const float*)d_in[10];

    const int SME = 128 * SGP * 4;   // 67584 bytes (gates region dominates)
    cudaFuncSetAttribute(k_step, cudaFuncAttributeMaxDynamicSharedMemorySize, SME);

    void *pWh0, *pWx0, *pB0, *pW1, *pB1, *pZ, *pC0, *pC1, *pSeq, *pH2a, *pH2b, *pH2f;
    cudaGetSymbolAddress(&pWh0, g_Wh0);
    cudaGetSymbolAddress(&pWx0, g_Wx0);
    cudaGetSymbolAddress(&pB0,  g_bias0);
    cudaGetSymbolAddress(&pW1,  g_W1);
    cudaGetSymbolAddress(&pB1,  g_bias1);
    cudaGetSymbolAddress(&pZ,   g_zero16);
    cudaGetSymbolAddress(&pC0,  g_c0);
    cudaGetSymbolAddress(&pC1,  g_c1);
    cudaGetSymbolAddress(&pSeq, g_h1seq);
    cudaGetSymbolAddress(&pH2a, g_h2a);
    cudaGetSymbolAddress(&pH2b, g_h2b);
    cudaGetSymbolAddress(&pH2f, g_h2f);

    __half* Wh0  = (__half*)pWh0;
    float*  Wx0  = (float*)pWx0;
    float*  bias0= (float*)pB0;
    __half* W1   = (__half*)pW1;
    float*  bias1= (float*)pB1;
    __half* z16  = (__half*)pZ;
    float*  c0   = (float*)pC0;
    float*  c1   = (float*)pC1;
    __half* seq  = (__half*)pSeq;
    __half* h2a  = (__half*)pH2a;
    __half* h2b  = (__half*)pH2b;
    float*  h2f  = (float*)pH2f;

    k_init<<<256, 256>>>();
    k_pack0<<<512, 256>>>(W_ih0, W_hh0, b_ih0, b_hh0);
    k_pack1<<<1024, 256>>>(W_ih1, W_hh1, b_ih1, b_hh1);

    dim3 grid(BN == 128 ? G_ / BN : 8, B_ / BM);
    dim3 blk(256);

    // layer 0: state chain lives inside h1seq itself
    for (int t = 0; t < T_; t++) {
        const __half* src = (t == 0) ? z16 : (seq + (size_t)(t - 1) * B_ * H_);
        __half* dst = seq + (size_t)t * B_ * H_;
        k_step<<<grid, blk, SME>>>(src, (const __half*)nullptr, Wh0, H_, bias0,
                                   x, t, Wx0, c0, dst, (float*)nullptr);
    }

    // layer 1: fused input projection (K=512), ping-pong h state
    for (int t = 0; t < T_; t++) {
        const __half* xpart = seq + (size_t)t * B_ * H_;
        const __half* hsrc = (t == 0) ? z16 : (((t - 1) & 1) ? h2b : h2a);
        __half* dst = (t & 1) ? h2b : h2a;
        float* fdst = (t == T_ - 1) ? h2f : (float*)nullptr;
        k_step<<<grid, blk, SME>>>(xpart, hsrc, W1, 2 * H_, bias1,
                                   (const float*)nullptr, 0, (const float*)nullptr,
                                   c1, dst, fdst);
    }

    k_fc<<<B_, dim3(32, 6)>>>(h2f, W_fc, b_fc, (float*)d_out);
}

// round 2
// speedup vs baseline: 1.0010x; 1.0010x over previous
#include <cuda_runtime.h>
#include <cuda_fp16.h>
#include <cstdint>
#include <cstddef>

#define B_ 2048
#define T_ 200
#define D_ 4
#define H_ 256
#define G_ 1024   // 4*H

#define BM 128
#define BN 128
#define BK 64
#define SGP 132   // gate smem pitch (floats)

// ------------------------- device scratch (no allocs allowed) -------------------------
__device__ __align__(128) __half g_Wh0[G_ * H_];          // [1024][256] packed, gate-interleaved rows
__device__ __align__(128) float  g_Wx0[G_ * D_];          // [1024][4]
__device__ __align__(128) float  g_bias0[G_];
__device__ __align__(128) __half g_W1[G_ * 2 * H_];       // [1024][512]: cols 0..255 = W_ih1, 256..511 = W_hh1
__device__ __align__(128) float  g_bias1[G_];
__device__ __align__(128) __half g_zero16[B_ * H_];       // zero h for t=0 (never written after init)
__device__ __align__(128) float  g_c0[B_ * H_];
__device__ __align__(128) float  g_c1[B_ * H_];
__device__ __align__(128) __half g_h1seq[(size_t)T_ * B_ * H_];  // layer0 output sequence (and its own state chain)
__device__ __align__(128) __half g_h2a[B_ * H_];
__device__ __align__(128) __half g_h2b[B_ * H_];
__device__ __align__(128) float  g_h2f[B_ * H_];          // fp32 h2 at t = T-1 (FC input)

// ------------------------- init / pack -------------------------
__global__ void k_init() {
    int stride = gridDim.x * blockDim.x;
    for (int i = blockIdx.x * blockDim.x + threadIdx.x; i < B_ * H_; i += stride) {
        g_zero16[i] = __float2half(0.f);
        g_c0[i] = 0.f;
        g_c1[i] = 0.f;
    }
}

__global__ void k_pack0(const float* __restrict__ W_ih0, const float* __restrict__ W_hh0,
                        const float* __restrict__ b_ih0, const float* __restrict__ b_hh0) {
    int stride = gridDim.x * blockDim.x;
    for (int i = blockIdx.x * blockDim.x + threadIdx.x; i < G_ * H_; i += stride) {
        int n = i >> 8;          // packed gate-col 0..1023
        int k = i & 255;
        int j = n >> 2, g = n & 3;
        int orow = g * H_ + j;   // original row in [4H, *] layout
        g_Wh0[i] = __float2half(W_hh0[orow * H_ + k]);
        if (k < D_) g_Wx0[n * D_ + k] = W_ih0[orow * D_ + k];
        if (k == 0) g_bias0[n] = b_ih0[orow] + b_hh0[orow];
    }
}

__global__ void k_pack1(const float* __restrict__ W_ih1, const float* __restrict__ W_hh1,
                        const float* __restrict__ b_ih1, const float* __restrict__ b_hh1) {
    int stride = gridDim.x * blockDim.x;
    for (int i = blockIdx.x * blockDim.x + threadIdx.x; i < G_ * 2 * H_; i += stride) {
        int n = i >> 9;
        int k = i & 511;
        int j = n >> 2, g = n & 3;
        int orow = g * H_ + j;
        float v = (k < H_) ? W_ih1[orow * H_ + k] : W_hh1[orow * H_ + (k - H_)];
        g_W1[i] = __float2half(v);
        if (k == 0) g_bias1[n] = b_ih1[orow] + b_hh1[orow];
    }
}

// ------------------------- fused LSTM step (GEMM + pointwise) -------------------------
// gates[b, n] = sum_k A[b,k] * W[n,k]  (+ bias + optional x@Wx), n gate-interleaved.
// A = concat(a0[256], a1[256]) for KTOT=512; a0 only for KTOT=256.
__global__ __launch_bounds__(256, 1)
void k_step(const __half* __restrict__ a0, const __half* __restrict__ a1,
            const __half* __restrict__ W, int KTOT,
            const float* __restrict__ bias,
            const float* __restrict__ x, int t,               // x: [B,T,4] (layer0) or null
            const float* __restrict__ Wx,                     // [1024][4] or null
            float* __restrict__ c,
            __half* __restrict__ hout,
            float* __restrict__ houtf)
{
    extern __shared__ char smem[];
    __half* sAbase = (__half*)smem;                 // 2 stages x 16KB
    __half* sBbase = (__half*)(smem + 32768);       // 2 stages x 16KB
    float*  sg     = (float*)smem;                  // reused after GEMM: 128 x 132 fp32 (67.5KB)

    const int tid  = threadIdx.x;
    const int lane = tid & 31;
    const int warp = tid >> 5;
    const int wm = warp & 3;    // 4 M-warps (32 rows each)
    const int wn = warp >> 2;   // 2 N-warps (64 cols each)
    const int mbase = blockIdx.y * BM;
    const int nbase = blockIdx.x * BN;

    // ldmatrix per-thread decode
    const int lg = lane >> 3;
    const int lr = lane & 7;
    const int a_rowoff = lr + ((lg & 1) << 3);   // within m16 tile
    const int a_half   = lg >> 1;                // 0: k 0..7, 1: k 8..15
    const int b_rowoff = lr + ((lg >> 1) << 3);  // within 16 n-rows
    const int b_half   = lg & 1;

    float acc[2][8][4];
#pragma unroll
    for (int mi = 0; mi < 2; mi++)
#pragma unroll
        for (int nj = 0; nj < 8; nj++)
#pragma unroll
            for (int e = 0; e < 4; e++) acc[mi][nj][e] = 0.f;

    const int NKC = KTOT / BK;

    auto load_tiles = [&](int kc, int buf) {
        const int k0 = kc * BK;
        const __half* asrc = (k0 < H_) ? (a0 + k0) : (a1 + (k0 - H_));
        __half* sA = sAbase + buf * (BM * BK);
        __half* sB = sBbase + buf * (BN * BK);
#pragma unroll
        for (int i = 0; i < 4; i++) {
            int lin = tid + i * 256;          // 0..1023: 128 rows x 8 chunks of 16B
            int r = lin >> 3;
            int cch = lin & 7;
            int sc = cch ^ (r & 7);
            {   // A tile: rows = batch, stride H_ halves
                const __half* gp = asrc + (size_t)(mbase + r) * H_ + cch * 8;
                uint32_t sa = (uint32_t)__cvta_generic_to_shared(sA + r * BK + sc * 8);
                asm volatile("cp.async.cg.shared.global [%0], [%1], 16;\n" :: "r"(sa), "l"(gp));
            }
            {   // B tile: rows = gate col, stride KTOT halves
                const __half* gp = W + (size_t)(nbase + r) * KTOT + k0 + cch * 8;
                uint32_t sa = (uint32_t)__cvta_generic_to_shared(sB + r * BK + sc * 8);
                asm volatile("cp.async.cg.shared.global [%0], [%1], 16;\n" :: "r"(sa), "l"(gp));
            }
        }
        asm volatile("cp.async.commit_group;\n");
    };

    load_tiles(0, 0);

#pragma unroll 1
    for (int kc = 0; kc < NKC; kc++) {
        asm volatile("cp.async.wait_group 0;\n");
        __syncthreads();
        const int cur = kc & 1;
        if (kc + 1 < NKC) load_tiles(kc + 1, cur ^ 1);

        __half* sA = sAbase + cur * (BM * BK);
        __half* sB = sBbase + cur * (BN * BK);

#pragma unroll
        for (int k16 = 0; k16 < BK / 16; k16++) {
            uint32_t afr[2][4];
#pragma unroll
            for (int mi = 0; mi < 2; mi++) {
                int r = wm * 32 + mi * 16 + a_rowoff;
                int cch = (k16 * 2 + a_half) ^ (r & 7);
                uint32_t ad = (uint32_t)__cvta_generic_to_shared(sA + r * BK + cch * 8);
                asm volatile("ldmatrix.sync.aligned.m8n8.x4.shared.b16 {%0,%1,%2,%3}, [%4];\n"
                             : "=r"(afr[mi][0]), "=r"(afr[mi][1]), "=r"(afr[mi][2]), "=r"(afr[mi][3])
                             : "r"(ad));
            }
            uint32_t bfr[4][4];
#pragma unroll
            for (int np = 0; np < 4; np++) {
                int r = wn * 64 + np * 16 + b_rowoff;
                int cch = (k16 * 2 + b_half) ^ (r & 7);
                uint32_t ad = (uint32_t)__cvta_generic_to_shared(sB + r * BK + cch * 8);
                asm volatile("ldmatrix.sync.aligned.m8n8.x4.shared.b16 {%0,%1,%2,%3}, [%4];\n"
                             : "=r"(bfr[np][0]), "=r"(bfr[np][1]), "=r"(bfr[np][2]), "=r"(bfr[np][3])
                             : "r"(ad));
            }
#pragma unroll
            for (int mi = 0; mi < 2; mi++)
#pragma unroll
                for (int nj = 0; nj < 8; nj++) {
                    uint32_t b0 = bfr[nj >> 1][(nj & 1) * 2 + 0];
                    uint32_t b1 = bfr[nj >> 1][(nj & 1) * 2 + 1];
                    asm volatile(
                        "mma.sync.aligned.m16n8k16.row.col.f32.f16.f16.f32 "
                        "{%0,%1,%2,%3}, {%4,%5,%6,%7}, {%8,%9}, {%0,%1,%2,%3};\n"
                        : "+f"(acc[mi][nj][0]), "+f"(acc[mi][nj][1]),
                          "+f"(acc[mi][nj][2]), "+f"(acc[mi][nj][3])
                        : "r"(afr[mi][0]), "r"(afr[mi][1]), "r"(afr[mi][2]), "r"(afr[mi][3]),
                          "r"(b0), "r"(b1));
                }
        }
    }
    __syncthreads();   // all smem reads done; safe to overwrite with gates

    // scatter accumulators to gate smem
#pragma unroll
    for (int mi = 0; mi < 2; mi++)
#pragma unroll
        for (int nj = 0; nj < 8; nj++) {
            int r0 = wm * 32 + mi * 16 + (lane >> 2);
            int c0 = wn * 64 + nj * 8 + (lane & 3) * 2;
            sg[r0 * SGP + c0]           = acc[mi][nj][0];
            sg[r0 * SGP + c0 + 1]       = acc[mi][nj][1];
            sg[(r0 + 8) * SGP + c0]     = acc[mi][nj][2];
            sg[(r0 + 8) * SGP + c0 + 1] = acc[mi][nj][3];
        }
    __syncthreads();

    // pointwise LSTM cell update: each thread handles (row, hidden) pairs
    for (int idx = tid; idx < BM * 32; idx += 256) {
        int r  = idx >> 5;
        int jh = idx & 31;
        int b  = mbase + r;
        int nloc = jh * 4;
        int ng = nbase + nloc;           // global packed gate col of gate i

        float gi = sg[r * SGP + nloc + 0] + bias[ng + 0];
        float gf = sg[r * SGP + nloc + 1] + bias[ng + 1];
        float gg = sg[r * SGP + nloc + 2] + bias[ng + 2];
        float go = sg[r * SGP + nloc + 3] + bias[ng + 3];

        if (x) {  // layer0: tiny D=4 input projection, exact fp32
            const float* xr = x + ((size_t)b * T_ + t) * D_;
            float x0 = xr[0], x1 = xr[1], x2 = xr[2], x3 = xr[3];
            const float* w = Wx + (size_t)ng * D_;
            gi += x0 * w[0]  + x1 * w[1]  + x2 * w[2]  + x3 * w[3];
            gf += x0 * w[4]  + x1 * w[5]  + x2 * w[6]  + x3 * w[7];
            gg += x0 * w[8]  + x1 * w[9]  + x2 * w[10] + x3 * w[11];
            go += x0 * w[12] + x1 * w[13] + x2 * w[14] + x3 * w[15];
        }

        float i_ = 1.f / (1.f + expf(-gi));
        float f_ = 1.f / (1.f + expf(-gf));
        float g_ = tanhf(gg);
        float o_ = 1.f / (1.f + expf(-go));

        int jglob = (nbase >> 2) + jh;
        size_t ci = (size_t)b * H_ + jglob;
        float cn = f_ * c[ci] + i_ * g_;
        c[ci] = cn;
        float h = o_ * tanhf(cn);
        hout[ci] = __float2half(h);
        if (houtf) houtf[ci] = h;
    }
}

// ------------------------- final FC: out = h2_last @ W_fc.T + b_fc -------------------------
__global__ void k_fc(const float* __restrict__ h, const float* __restrict__ Wfc,
                     const float* __restrict__ bfc, float* __restrict__ out) {
    int b = blockIdx.x;
    int o = threadIdx.y;   // 0..5
    int lane = threadIdx.x;
    const float* hr = h + (size_t)b * H_;
    const float* wr = Wfc + (size_t)o * H_;
    float s = 0.f;
    for (int j = lane; j < H_; j += 32) s += hr[j] * wr[j];
#pragma unroll
    for (int off = 16; off; off >>= 1) s += __shfl_xor_sync(0xffffffffu, s, off);
    if (lane == 0) out[b * 6 + o] = s + bfc[o];
}

// ------------------------- host -------------------------
extern "C" void kernel_launch(void* const* d_in, const int* in_sizes, int n_in,
                              void* d_out, int out_size) {
    const float* x     = (const float*)d_in[0];
    const float* W_ih0 = (const float*)d_in[1];
    const float* W_hh0 = (const float*)d_in[2];
    const float* b_ih0 = (const float*)d_in[3];
    const float* b_hh0 = (const float*)d_in[4];
    const float* W_ih1 = (const float*)d_in[5];
    const float* W_hh1 = (const float*)d_in[6];
    const float* b_ih1 = (const float*)d_in[7];
    const float* b_hh1 = (const float*)d_in[8];
    const float* W_fc  = (const float*)d_in[9];
    const float* b_fc  = (const float*)d_in[10];

    const int SME = 128 * SGP * 4;   // 67584 bytes (gates region dominates)
    cudaFuncSetAttribute(k_step, cudaFuncAttributeMaxDynamicSharedMemorySize, SME);

    void *pWh0, *pWx0, *pB0, *pW1, *pB1, *pZ, *pC0, *pC1, *pSeq, *pH2a, *pH2b, *pH2f;
    cudaGetSymbolAddress(&pWh0, g_Wh0);
    cudaGetSymbolAddress(&pWx0, g_Wx0);
    cudaGetSymbolAddress(&pB0,  g_bias0);
    cudaGetSymbolAddress(&pW1,  g_W1);
    cudaGetSymbolAddress(&pB1,  g_bias1);
    cudaGetSymbolAddress(&pZ,   g_zero16);
    cudaGetSymbolAddress(&pC0,  g_c0);
    cudaGetSymbolAddress(&pC1,  g_c1);
    cudaGetSymbolAddress(&pSeq, g_h1seq);
    cudaGetSymbolAddress(&pH2a, g_h2a);
    cudaGetSymbolAddress(&pH2b, g_h2b);
    cudaGetSymbolAddress(&pH2f, g_h2f);

    __half* Wh0  = (__half*)pWh0;
    float*  Wx0  = (float*)pWx0;
    float*  bias0= (float*)pB0;
    __half* W1   = (__half*)pW1;
    float*  bias1= (float*)pB1;
    __half* z16  = (__half*)pZ;
    float*  c0   = (float*)pC0;
    float*  c1   = (float*)pC1;
    __half* seq  = (__half*)pSeq;
    __half* h2a  = (__half*)pH2a;
    __half* h2b  = (__half*)pH2b;
    float*  h2f  = (float*)pH2f;

    k_init<<<256, 256>>>();
    k_pack0<<<512, 256>>>(W_ih0, W_hh0, b_ih0, b_hh0);
    k_pack1<<<1024, 256>>>(W_ih1, W_hh1, b_ih1, b_hh1);

    dim3 grid(BN == 128 ? G_ / BN : 8, B_ / BM);
    dim3 blk(256);

    // layer 0: state chain lives inside h1seq itself
    for (int t = 0; t < T_; t++) {
        const __half* src = (t == 0) ? z16 : (seq + (size_t)(t - 1) * B_ * H_);
        __half* dst = seq + (size_t)t * B_ * H_;
        k_step<<<grid, blk, SME>>>(src, (const __half*)nullptr, Wh0, H_, bias0,
                                   x, t, Wx0, c0, dst, (float*)nullptr);
    }

    // layer 1: fused input projection (K=512), ping-pong h state
    for (int t = 0; t < T_; t++) {
        const __half* xpart = seq + (size_t)t * B_ * H_;
        const __half* hsrc = (t == 0) ? z16 : (((t - 1) & 1) ? h2b : h2a);
        __half* dst = (t & 1) ? h2b : h2a;
        float* fdst = (t == T_ - 1) ? h2f : (float*)nullptr;
        k_step<<<grid, blk, SME>>>(xpart, hsrc, W1, 2 * H_, bias1,
                                   (const float*)nullptr, 0, (const float*)nullptr,
                                   c1, dst, fdst);
    }

    k_fc<<<B_, dim3(32, 6)>>>(h2f, W_fc, b_fc, (float*)d_out);
}

// round 3
// speedup vs baseline: 1.3796x; 1.3782x over previous
#include <cuda_runtime.h>
#include <cuda_fp16.h>
#include <cstdint>
#include <cstddef>

#define B_ 2048
#define T_ 200
#define D_ 4
#define H_ 256
#define G_ 1024
#define CL 8
#define THREADS 256

// smem layout (bytes)
#define SW_OFF   0                         // 8 chunks * 16KB = 128KB
#define RING_OFF (8*16384)                 // 4 slots * 16KB
#define HSTG_OFF (RING_OFF + 4*16384)      // 16KB
#define XROW_OFF (HSTG_OFF + 16384)        // 2KB
#define SWX_OFF  (XROW_OFF + 2048)         // 2KB
#define SMEM_TOTAL (SWX_OFF + 2048)        // 217088

// ---------------- device globals ----------------
__device__ __align__(128) __half g_Wh0[G_ * H_];
__device__ __align__(128) float  g_Wx0[G_ * D_];
__device__ __align__(128) float  g_b0[G_];
__device__ __align__(128) __half g_W1[G_ * 2 * H_];
__device__ __align__(128) float  g_b1[G_];
__device__ __align__(128) __half g_zero[B_ * H_];
__device__ __align__(128) __half g_h1seq[(size_t)T_ * B_ * H_];
__device__ __align__(128) __half g_h2a[B_ * H_];
__device__ __align__(128) __half g_h2b[B_ * H_];
__device__ __align__(128) float  g_h2f[B_ * H_];

// ---------------- init / pack ----------------
__global__ void k_init() {
    int stride = gridDim.x * blockDim.x;
    for (int i = blockIdx.x * blockDim.x + threadIdx.x; i < B_ * H_; i += stride)
        g_zero[i] = __float2half(0.f);
}

__global__ void k_pack0(const float* __restrict__ W_ih0, const float* __restrict__ W_hh0,
                        const float* __restrict__ b_ih0, const float* __restrict__ b_hh0) {
    int stride = gridDim.x * blockDim.x;
    for (int i = blockIdx.x * blockDim.x + threadIdx.x; i < G_ * H_; i += stride) {
        int n = i >> 8, k = i & 255;
        int j = n >> 2, g = n & 3;
        int orow = g * H_ + j;
        g_Wh0[i] = __float2half(W_hh0[orow * H_ + k]);
        if (k < D_) g_Wx0[n * D_ + k] = W_ih0[orow * D_ + k];
        if (k == 0) g_b0[n] = b_ih0[orow] + b_hh0[orow];
    }
}

__global__ void k_pack1(const float* __restrict__ W_ih1, const float* __restrict__ W_hh1,
                        const float* __restrict__ b_ih1, const float* __restrict__ b_hh1) {
    int stride = gridDim.x * blockDim.x;
    for (int i = blockIdx.x * blockDim.x + threadIdx.x; i < G_ * 2 * H_; i += stride) {
        int n = i >> 9, k = i & 511;
        int j = n >> 2, g = n & 3;
        int orow = g * H_ + j;
        float v = (k < H_) ? W_ih1[orow * H_ + k] : W_hh1[orow * H_ + (k - H_)];
        g_W1[i] = __float2half(v);
        if (k == 0) g_b1[n] = b_ih1[orow] + b_hh1[orow];
    }
}

// ---------------- helpers ----------------
__device__ __forceinline__ void cpa16(void* sdst, const void* gsrc) {
    uint32_t sa = (uint32_t)__cvta_generic_to_shared(sdst);
    asm volatile("cp.async.cg.shared.global [%0], [%1], 16;\n" :: "r"(sa), "l"(gsrc));
}
__device__ __forceinline__ void cpcommit() { asm volatile("cp.async.commit_group;\n"); }
__device__ __forceinline__ void cpwait(int n) {
    if (n <= 0)      asm volatile("cp.async.wait_group 0;\n");
    else if (n == 1) asm volatile("cp.async.wait_group 1;\n");
    else             asm volatile("cp.async.wait_group 2;\n");
}
__device__ __forceinline__ void clsync() {
    asm volatile("barrier.cluster.arrive.aligned;\n" ::: "memory");
    asm volatile("barrier.cluster.wait.aligned;\n" ::: "memory");
}
__device__ __forceinline__ float sig_(float x) {
    float e; asm("ex2.approx.ftz.f32 %0, %1;" : "=f"(e) : "f"(x * -1.44269504f));
    float r; asm("rcp.approx.ftz.f32 %0, %1;" : "=f"(r) : "f"(1.0f + e));
    return r;
}
__device__ __forceinline__ float tanh_(float x) { return __fmaf_rn(2.f, sig_(2.f * x), -1.f); }

// A chunk: [128 rows x 64 halves], global row stride H_
__device__ __forceinline__ void load_chunkA(const __half* gp, __half* slot, int tid) {
#pragma unroll
    for (int i = 0; i < 4; i++) {
        int lin = tid + i * THREADS;
        int r = lin >> 3, cch = lin & 7, sc = cch ^ (r & 7);
        cpa16(slot + r * 64 + sc * 8, gp + (size_t)r * H_ + cch * 8);
    }
}
// W chunk: global row stride ws
__device__ __forceinline__ void load_chunkW(const __half* gp, int ws, __half* dst, int tid) {
#pragma unroll
    for (int i = 0; i < 4; i++) {
        int lin = tid + i * THREADS;
        int r = lin >> 3, cch = lin & 7, sc = cch ^ (r & 7);
        cpa16(dst + r * 64 + sc * 8, gp + (size_t)r * ws + cch * 8);
    }
}

// ---------------- one LSTM step ----------------
template<bool XPROJ, int NC, int NCX>
__device__ __forceinline__ void lstm_step(
    const __half* __restrict__ xsrc,   // chunks 0..NCX-1 (pre-offset mbase*H_)
    const __half* __restrict__ hsrc,   // chunks NCX..NC-1
    const float*  __restrict__ xrow_g, // x + (mbase*T + t)*D  (XPROJ only)
    __half* __restrict__ hout,         // + mbase*H_ + rank*32 (null if final)
    float*  __restrict__ hfout,        // fp32 final out, or null
    float* c, const float* biasr,
    char* smem, int tid, int lane, int wm, int wn,
    int a_rowoff, int a_half, int b_rowoff, int b_half)
{
    __half* sW   = (__half*)(smem + SW_OFF);
    __half* ring = (__half*)(smem + RING_OFF);

    float acc[2][8][4];
#pragma unroll
    for (int mi = 0; mi < 2; mi++)
#pragma unroll
        for (int nj = 0; nj < 8; nj++)
#pragma unroll
            for (int e = 0; e < 4; e++) acc[mi][nj][e] = 0.f;

    auto chunk_ptr = [&](int kc) -> const __half* {
        return (kc < NCX) ? (xsrc + kc * 64) : (hsrc + (kc - NCX) * 64);
    };

    if (XPROJ && tid < 128)
        cpa16((float*)(smem + XROW_OFF) + tid * 4, xrow_g + (size_t)tid * (T_ * D_));
    load_chunkA(chunk_ptr(0), ring + 0 * 8192, tid); cpcommit();
    load_chunkA(chunk_ptr(1), ring + 1 * 8192, tid); cpcommit();
    load_chunkA(chunk_ptr(2), ring + 2 * 8192, tid); cpcommit();

#pragma unroll 1
    for (int kc = 0; kc < NC; kc++) {
        int nwait = NC - 1 - kc; if (nwait > 2) nwait = 2;
        cpwait(nwait);
        __syncthreads();
        if (kc + 3 < NC) { load_chunkA(chunk_ptr(kc + 3), ring + ((kc + 3) & 3) * 8192, tid); cpcommit(); }

        __half* sA = ring + (kc & 3) * 8192;
        __half* sB = sW + kc * 8192;

#pragma unroll
        for (int k16 = 0; k16 < 4; k16++) {
            uint32_t afr[2][4];
#pragma unroll
            for (int mi = 0; mi < 2; mi++) {
                int r = wm * 32 + mi * 16 + a_rowoff;
                int cch = (k16 * 2 + a_half) ^ (r & 7);
                uint32_t ad = (uint32_t)__cvta_generic_to_shared(sA + r * 64 + cch * 8);
                asm volatile("ldmatrix.sync.aligned.m8n8.x4.shared.b16 {%0,%1,%2,%3}, [%4];\n"
                             : "=r"(afr[mi][0]), "=r"(afr[mi][1]), "=r"(afr[mi][2]), "=r"(afr[mi][3])
                             : "r"(ad));
            }
            uint32_t bfr[4][4];
#pragma unroll
            for (int np = 0; np < 4; np++) {
                int r = wn * 64 + np * 16 + b_rowoff;
                int cch = (k16 * 2 + b_half) ^ (r & 7);
                uint32_t ad = (uint32_t)__cvta_generic_to_shared(sB + r * 64 + cch * 8);
                asm volatile("ldmatrix.sync.aligned.m8n8.x4.shared.b16 {%0,%1,%2,%3}, [%4];\n"
                             : "=r"(bfr[np][0]), "=r"(bfr[np][1]), "=r"(bfr[np][2]), "=r"(bfr[np][3])
                             : "r"(ad));
            }
#pragma unroll
            for (int mi = 0; mi < 2; mi++)
#pragma unroll
                for (int nj = 0; nj < 8; nj++) {
                    uint32_t b0 = bfr[nj >> 1][(nj & 1) * 2 + 0];
                    uint32_t b1 = bfr[nj >> 1][(nj & 1) * 2 + 1];
                    asm volatile(
                        "mma.sync.aligned.m16n8k16.row.col.f32.f16.f16.f32 "
                        "{%0,%1,%2,%3}, {%4,%5,%6,%7}, {%8,%9}, {%0,%1,%2,%3};\n"
                        : "+f"(acc[mi][nj][0]), "+f"(acc[mi][nj][1]),
                          "+f"(acc[mi][nj][2]), "+f"(acc[mi][nj][3])
                        : "r"(afr[mi][0]), "r"(afr[mi][1]), "r"(afr[mi][2]), "r"(afr[mi][3]),
                          "r"(b0), "r"(b1));
                }
        }
    }

    // ---------- pointwise in registers ----------
    const int q = lane & 3;
    const bool oddq = (q & 1) != 0;
    const bool fin = (hfout != nullptr);
    float*  xrow  = (float*)(smem + XROW_OFF);
    float*  sWx   = (float*)(smem + SWX_OFF);
    __half* hstg  = (__half*)(smem + HSTG_OFF);
    float*  hstgf = (float*)(smem + HSTG_OFF);

#pragma unroll
    for (int mi = 0; mi < 2; mi++) {
        int r0 = wm * 32 + mi * 16 + (lane >> 2);
        float4 xlo = {0,0,0,0}, xhi = {0,0,0,0};
        if (XPROJ) {
            xlo = *(const float4*)&xrow[r0 * 4];
            xhi = *(const float4*)&xrow[(r0 + 8) * 4];
        }
#pragma unroll
        for (int nj = 0; nj < 8; nj++) {
            float a0 = acc[mi][nj][0] + biasr[nj * 2 + 0];
            float a1 = acc[mi][nj][1] + biasr[nj * 2 + 1];
            float a2 = acc[mi][nj][2] + biasr[nj * 2 + 0];
            float a3 = acc[mi][nj][3] + biasr[nj * 2 + 1];
            if (XPROJ) {
                int cl = wn * 64 + nj * 8 + q * 2;   // local col in CTA slice
                float4 w0 = *(const float4*)&sWx[cl * 4];
                float4 w1 = *(const float4*)&sWx[cl * 4 + 4];
                a0 += xlo.x * w0.x + xlo.y * w0.y + xlo.z * w0.z + xlo.w * w0.w;
                a1 += xlo.x * w1.x + xlo.y * w1.y + xlo.z * w1.z + xlo.w * w1.w;
                a2 += xhi.x * w0.x + xhi.y * w0.y + xhi.z * w0.z + xhi.w * w0.w;
                a3 += xhi.x * w1.x + xhi.y * w1.y + xhi.z * w1.z + xhi.w * w1.w;
            }
            float e0 = __shfl_xor_sync(0xffffffffu, a0, 1);
            float e1 = __shfl_xor_sync(0xffffffffu, a1, 1);
            float e2 = __shfl_xor_sync(0xffffffffu, a2, 1);
            float e3 = __shfl_xor_sync(0xffffffffu, a3, 1);
            float gi, gf, gg, go; int row;
            if (!oddq) { gi = a0; gf = a1; gg = e0; go = e1; row = r0; }
            else       { gi = e2; gf = e3; gg = a2; go = a3; row = r0 + 8; }
            int ci = mi * 8 + nj;
            float iv = sig_(gi), fv = sig_(gf), gv = tanh_(gg), ov = sig_(go);
            float cn = fv * c[ci] + iv * gv;
            c[ci] = cn;
            float h = ov * tanh_(cn);
            int jl = wn * 16 + nj * 2 + (q >> 1);    // local hidden 0..31
            if (fin) hstgf[row * 32 + jl] = h;
            else     hstg[row * 32 + jl] = __float2half(h);
        }
    }
    __syncthreads();

    if (!fin) {
#pragma unroll
        for (int p = 0; p < 8; p++) {
            int row = p * 16 + (tid >> 4);
            int cc  = (tid & 15) * 2;
            *(uint32_t*)(hout + (size_t)row * H_ + cc) = *(uint32_t*)&hstg[row * 32 + cc];
        }
    } else {
#pragma unroll
        for (int p = 0; p < 16; p++) {
            int row = p * 8 + (tid >> 5);
            int cc  = tid & 31;
            hfout[(size_t)row * H_ + cc] = hstgf[row * 32 + cc];
        }
    }
    clsync();   // orders h stores (release) before any peer's next-step loads (acquire)
}

// ---------------- persistent kernel ----------------
__global__ void __cluster_dims__(CL, 1, 1) __launch_bounds__(THREADS, 1)
k_lstm(const float* __restrict__ x)
{
    extern __shared__ char smem[];
    const int tid  = threadIdx.x;
    const int lane = tid & 31;
    const int warp = tid >> 5;
    const int wm = warp & 3;
    const int wn = warp >> 2;
    const int rank  = blockIdx.x;          // 0..7 within cluster
    const int mbase = blockIdx.y * 128;    // batch slice
    const int nbase = rank * 128;          // gate-col slice
    const int q = lane & 3;

    const int lg = lane >> 3, lr = lane & 7;
    const int a_rowoff = lr + ((lg & 1) << 3);
    const int a_half   = lg >> 1;
    const int b_rowoff = lr + ((lg >> 1) << 3);
    const int b_half   = lg & 1;

    __half* sW  = (__half*)(smem + SW_OFF);
    float*  sWx = (float*)(smem + SWX_OFF);

    float biasr[16], c[16];

    // ---- phase A: layer 0 (K=256) ----
#pragma unroll
    for (int kc = 0; kc < 4; kc++)
        load_chunkW(g_Wh0 + (size_t)nbase * H_ + kc * 64, H_, sW + kc * 8192, tid);
    if (tid < 128) cpa16(sWx + tid * 4, g_Wx0 + (size_t)(nbase + tid) * D_);
    cpcommit(); cpwait(0); __syncthreads();
#pragma unroll
    for (int nj = 0; nj < 8; nj++) {
        biasr[nj * 2 + 0] = g_b0[nbase + wn * 64 + nj * 8 + q * 2 + 0];
        biasr[nj * 2 + 1] = g_b0[nbase + wn * 64 + nj * 8 + q * 2 + 1];
    }
#pragma unroll
    for (int i = 0; i < 16; i++) c[i] = 0.f;

    const __half* zero_m = g_zero + (size_t)mbase * H_;
#pragma unroll 1
    for (int t = 0; t < T_; t++) {
        const __half* hs = (t == 0) ? zero_m : (g_h1seq + ((size_t)(t - 1) * B_ + mbase) * H_);
        __half* dst = g_h1seq + ((size_t)t * B_ + mbase) * H_ + rank * 32;
        lstm_step<true, 4, 0>(nullptr, hs, x + ((size_t)mbase * T_ + t) * D_,
                              dst, nullptr, c, biasr, smem, tid, lane, wm, wn,
                              a_rowoff, a_half, b_rowoff, b_half);
    }

    // ---- phase B: layer 1 (K=512) ----
#pragma unroll
    for (int kc = 0; kc < 8; kc++)
        load_chunkW(g_W1 + (size_t)nbase * 2 * H_ + kc * 64, 2 * H_, sW + kc * 8192, tid);
    cpcommit(); cpwait(0); __syncthreads();
#pragma unroll
    for (int nj = 0; nj < 8; nj++) {
        biasr[nj * 2 + 0] = g_b1[nbase + wn * 64 + nj * 8 + q * 2 + 0];
        biasr[nj * 2 + 1] = g_b1[nbase + wn * 64 + nj * 8 + q * 2 + 1];
    }
#pragma unroll
    for (int i = 0; i < 16; i++) c[i] = 0.f;

#pragma unroll 1
    for (int t = 0; t < T_; t++) {
        const __half* xs = g_h1seq + ((size_t)t * B_ + mbase) * H_;
        const __half* hs = (t == 0) ? zero_m
                         : ((((t - 1) & 1) ? g_h2b : g_h2a) + (size_t)mbase * H_);
        bool fin = (t == T_ - 1);
        __half* dst = ((t & 1) ? g_h2b : g_h2a) + (size_t)mbase * H_ + rank * 32;
        float* fdst = fin ? (g_h2f + (size_t)mbase * H_ + rank * 32) : (float*)nullptr;
        lstm_step<false, 8, 4>(xs, hs, nullptr, fin ? (/*unused*/(__half*)nullptr) : dst,
                               fdst, c, biasr, smem, tid, lane, wm, wn,
                               a_rowoff, a_half, b_rowoff, b_half);
    }
}

// ---------------- final FC ----------------
__global__ void k_fc(const float* __restrict__ Wfc, const float* __restrict__ bfc,
                     float* __restrict__ out) {
    int b = blockIdx.x;
    int o = threadIdx.y;
    int lane = threadIdx.x;
    const float* hr = g_h2f + (size_t)b * H_;
    const float* wr = Wfc + (size_t)o * H_;
    float s = 0.f;
    for (int j = lane; j < H_; j += 32) s += hr[j] * wr[j];
#pragma unroll
    for (int off = 16; off; off >>= 1) s += __shfl_xor_sync(0xffffffffu, s, off);
    if (lane == 0) out[b * 6 + o] = s + bfc[o];
}

// ---------------- host ----------------
extern "C" void kernel_launch(void* const* d_in, const int* in_sizes, int n_in,
                              void* d_out, int out_size) {
    const float* x     = (const float*)d_in[0];
    const float* W_ih0 = (const float*)d_in[1];
    const float* W_hh0 = (const float*)d_in[2];
    const float* b_ih0 = (const float*)d_in[3];
    const float* b_hh0 = (const float*)d_in[4];
    const float* W_ih1 = (const float*)d_in[5];
    const float* W_hh1 = (const float*)d_in[6];
    const float* b_ih1 = (const float*)d_in[7];
    const float* b_hh1 = (const float*)d_in[8];
    const float* W_fc  = (const float*)d_in[9];
    const float* b_fc  = (const float*)d_in[10];

    static int attr_done = 0;
    if (!attr_done) {
        cudaFuncSetAttribute(k_lstm, cudaFuncAttributeMaxDynamicSharedMemorySize, SMEM_TOTAL);
        attr_done = 1;
    }

    k_init<<<256, 256>>>();
    k_pack0<<<512, 256>>>(W_ih0, W_hh0, b_ih0, b_hh0);
    k_pack1<<<1024, 256>>>(W_ih1, W_hh1, b_ih1, b_hh1);

    k_lstm<<<dim3(CL, 16), THREADS, SMEM_TOTAL>>>(x);

    k_fc<<<B_, dim3(32, 6)>>>(W_fc, b_fc, (float*)d_out);
}